// round 15
// baseline (speedup 1.0000x reference)
#include <cuda_runtime.h>
#include <cuda_fp16.h>
#include <math.h>
#include <stdint.h>

// ---------------------------------------------------------------------------
// Problem constants
// ---------------------------------------------------------------------------
namespace {
constexpr int B = 4;
constexpr int T = 2048;
constexpr int D = 1024;      // D_IN == D_OUT
constexpr int MPROJ = B * T; // 8192

// Scratch (allocation-free: __device__ globals)
__device__ __half g_x  [(size_t)MPROJ * D];  // 16 MB  fp16 input
__device__ __half g_w16[2][(size_t)D * D];   // 4 MB   fp16 Wq, Wk (row-major)
__device__ __half g_wtv[(size_t)D * D];      // 2 MB   fp16 Wv^T (n-major)
__device__ __half g_mt [(size_t)D * D];      // 2 MB   Mt[e][d] = (Wq Wk^T)^T
__device__ __half g_y  [(size_t)B * T * D];  // 16 MB  Y = X (Wq Wk^T)
__device__ __half g_vt [(size_t)B * D * T];  // 16 MB  V^T per batch
__device__ __half g_ph [(size_t)B * T * T];  // 32 MB  unnormalized probs fp16
} // namespace

// ---------------------------------------------------------------------------
// Helpers
// ---------------------------------------------------------------------------
__device__ __forceinline__ uint32_t smem_u32(const void* p) {
    uint32_t a;
    asm("{ .reg .u64 t; cvta.to.shared.u64 t, %1; cvt.u32.u64 %0, t; }"
        : "=r"(a) : "l"(p));
    return a;
}

__device__ __forceinline__ void cp16(uint32_t dst, const void* src) {
    asm volatile("cp.async.cg.shared.global [%0], [%1], 16;"
                 :: "r"(dst), "l"(src) : "memory");
}
#define CP_COMMIT()  asm volatile("cp.async.commit_group;" ::: "memory")
#define CP_WAIT(N)   asm volatile("cp.async.wait_group %0;" :: "n"(N) : "memory")
#define CP_WAIT_ALL() asm volatile("cp.async.wait_group 0;" ::: "memory")

__device__ __forceinline__ void ldsm4(uint32_t& r0, uint32_t& r1,
                                      uint32_t& r2, uint32_t& r3,
                                      uint32_t addr) {
    asm volatile("ldmatrix.sync.aligned.m8n8.x4.shared.b16 {%0,%1,%2,%3}, [%4];"
                 : "=r"(r0), "=r"(r1), "=r"(r2), "=r"(r3) : "r"(addr));
}

__device__ __forceinline__ void mma_f16(float c[4], const uint32_t a[4],
                                        const uint32_t b[2]) {
    asm volatile(
        "mma.sync.aligned.m16n8k16.row.col.f32.f16.f16.f32 "
        "{%0,%1,%2,%3}, {%4,%5,%6,%7}, {%8,%9}, {%0,%1,%2,%3};"
        : "+f"(c[0]), "+f"(c[1]), "+f"(c[2]), "+f"(c[3])
        : "r"(a[0]), "r"(a[1]), "r"(a[2]), "r"(a[3]), "r"(b[0]), "r"(b[1]));
}

// ---------------------------------------------------------------------------
// fp16 mma.sync GEMM core ("NT": both operands K-major).
//   C[m,n] += A[m,k] * Bp[n,k]
// CTA tile 128x128, BK=64 halves per mainloop iteration (a "double chunk" =
// two 16KB sub-tiles in the proven layout), 128 threads (4 warps, 2x2 grid),
// warp tile 64x64. Fragment-level software pipeline across the 4 K16 steps:
// LDSM(s0) -> cp.async burst -> LDSM(s1) -> HMMA(s0) -> LDSM(s2) -> HMMA(s1)
// -> LDSM(s3) -> HMMA(s2) -> HMMA(s3). One __syncthreads per 64 K (halved).
// 3-stage pipeline; stage = 32 KB; 96 KB smem -> 2 CTAs/SM.
// EPI: 1 = plain fp16 stores
//      2 = exp(s*SCALE - EXPC) with causal mask, fp16 stores (scores)
//      3 = fp32 stores scaled by inline per-row 1/sum of A (pv)
//      4 = fp16 transposed store via smem -> g_vt (V proj)
// ---------------------------------------------------------------------------
constexpr int STAGES = 3;
constexpr int STAGE_BYTES = 32768;           // 2 sub-tiles x (A 8KB + B 8KB)
constexpr int SMEM_BYTES = STAGES * STAGE_BYTES; // 98304
constexpr int NTHREADS = 128;
constexpr float SCALE = 0.03125f;  // 1/sqrt(1024)
constexpr float EXPC = 5.0f;       // fixed exp offset (cancels in normalize)

template <int EPI>
__device__ __forceinline__ void hgemm(const __half* __restrict__ A,
                                      const __half* __restrict__ Bp,
                                      void* __restrict__ Cv,
                                      int lda, int ldb, int ldc,
                                      int bm, int bn, int nChunks) {
    // nChunks counts BK=64 double-chunks.
    extern __shared__ float sm[];
    const uint32_t smem_base = smem_u32(sm);

    const int tid = threadIdx.x;
    const int lane = tid & 31;
    const int wid = tid >> 5;
    const int wr = wid >> 1;     // 0..1  (64-row slab)
    const int wc = wid & 1;      // 0..1  (64-col slab)
    const int gid = lane >> 2;   // 0..7
    const int tig = lane & 3;    // 0..3

    // ldmatrix lane roles (mapping validated R6/R7)
    const int a_row_off = ((lane >> 3) & 1) * 8 + (lane & 7);
    const int a_kg = lane >> 4;
    const int b_row_off = (lane >> 4) * 8 + (lane & 7);
    const int b_kg = (lane >> 3) & 1;

    // Issue one 16KB sub-tile pair (A+B, 32 halves of K) at byte offset off.
    auto issue_sub = [&](int k0, uint32_t off) {
        const uint32_t sA = smem_base + off;
        const uint32_t sB = sA + 8192;
#pragma unroll
        for (int l = 0; l < 4; l++) {               // A: 128 rows x 32 halves
            const int idx = tid + l * NTHREADS;
            const int m = idx >> 2, c = idx & 3;
            const uint32_t sw = ((m >> 1) & 3) << 2;
            cp16(sA + (uint32_t)(m * 16 + ((4 * c) ^ sw)) * 4,
                 A + (size_t)(bm + m) * lda + k0 + 8 * c);
        }
#pragma unroll
        for (int l = 0; l < 4; l++) {               // B: 128 rows x 32 halves
            const int idx = tid + l * NTHREADS;
            const int n = idx >> 2, c = idx & 3;
            const uint32_t sw = ((n >> 1) & 3) << 2;
            cp16(sB + (uint32_t)(n * 16 + ((4 * c) ^ sw)) * 4,
                 Bp + (size_t)(bn + n) * ldb + k0 + 8 * c);
        }
    };
    auto issue = [&](int chunk, int buf) {
        issue_sub(chunk * 64, (uint32_t)buf * STAGE_BYTES);
        issue_sub(chunk * 64 + 32, (uint32_t)buf * STAGE_BYTES + 16384);
    };

    float acc[4][8][4];
#pragma unroll
    for (int i = 0; i < 4; i++)
#pragma unroll
        for (int j = 0; j < 8; j++)
#pragma unroll
            for (int e = 0; e < 4; e++) acc[i][j][e] = 0.0f;

    float rsum[8]; // EPI==3: per-row A sums (rows i*16+gid, i*16+gid+8)
#pragma unroll
    for (int r = 0; r < 8; r++) rsum[r] = 0.0f;

    // Per-lane invariant fragment address pieces: low 16 = row*16, hi = swizzle
    uint32_t aw[4], bw[4];
#pragma unroll
    for (int i = 0; i < 4; i++) {
        const int row = wr * 64 + i * 16 + a_row_off;
        aw[i] = (uint32_t)(row * 16) | (((row >> 1) & 3) << 2) << 16;
    }
#pragma unroll
    for (int jp = 0; jp < 4; jp++) {
        const int row = wc * 64 + jp * 16 + b_row_off;
        bw[jp] = (uint32_t)(row * 16) | (((row >> 1) & 3) << 2) << 16;
    }

    // Fragment load for K16 step s (0..3) of the stage at base sbase.
    uint32_t afX[4][4], bfX[8][2], afY[4][4], bfY[8][2];
    auto ldsmA = [&](uint32_t (&af)[4][4], uint32_t (&bf)[8][2],
                     uint32_t sbase, int s) {
        const uint32_t sub = (uint32_t)(s >> 1) * 16384;
        const uint32_t w0 = (uint32_t)(s & 1) * 8;
        const uint32_t sa = sbase + sub;
        const uint32_t sb = sa + 8192;
#pragma unroll
        for (int i = 0; i < 4; i++) {
            const uint32_t g = (w0 + 4 * a_kg) ^ (aw[i] >> 16);
            ldsm4(af[i][0], af[i][1], af[i][2], af[i][3],
                  sa + (((aw[i] & 0xffffu) + g) << 2));
        }
#pragma unroll
        for (int jp = 0; jp < 4; jp++) {
            const uint32_t g = (w0 + 4 * b_kg) ^ (bw[jp] >> 16);
            ldsm4(bf[2 * jp][0], bf[2 * jp][1], bf[2 * jp + 1][0],
                  bf[2 * jp + 1][1], sb + (((bw[jp] & 0xffffu) + g) << 2));
        }
    };
    auto domma = [&](uint32_t (&af)[4][4], uint32_t (&bf)[8][2]) {
        if (EPI == 3) {
#pragma unroll
            for (int i = 0; i < 4; i++) {
                const __half2 h0 = __hadd2(
                    *reinterpret_cast<__half2*>(&af[i][0]),
                    *reinterpret_cast<__half2*>(&af[i][2]));
                const __half2 h1 = __hadd2(
                    *reinterpret_cast<__half2*>(&af[i][1]),
                    *reinterpret_cast<__half2*>(&af[i][3]));
                const float2 f0 = __half22float2(h0);
                const float2 f1 = __half22float2(h1);
                rsum[2 * i]     += f0.x + f0.y;
                rsum[2 * i + 1] += f1.x + f1.y;
            }
        }
#pragma unroll
        for (int i = 0; i < 4; i++)
#pragma unroll
            for (int j = 0; j < 8; j++) mma_f16(acc[i][j], af[i], bf[j]);
    };

    // Prologue (nChunks >= STAGES-1 = 2 always: pv min is 2)
#pragma unroll
    for (int s = 0; s < STAGES - 1; s++) {
        issue(s, s);
        CP_COMMIT();
    }

    int buf = 0;
    for (int t = 0; t < nChunks; t++) {
        CP_WAIT(STAGES - 2);
        __syncthreads();

        const uint32_t sbase = smem_base + (uint32_t)buf * STAGE_BYTES;

        // step 0 fragments
        ldsmA(afX, bfX, sbase, 0);

        // prefetch chunk t+STAGES-1 (independent work hides LDS latency)
        if (t + STAGES - 1 < nChunks) {
            int pbuf = buf + STAGES - 1;
            if (pbuf >= STAGES) pbuf -= STAGES;
            issue(t + STAGES - 1, pbuf);
        }
        CP_COMMIT();

        ldsmA(afY, bfY, sbase, 1);   // step 1 fragments
        domma(afX, bfX);             // HMMA step 0
        ldsmA(afX, bfX, sbase, 2);   // step 2 fragments
        domma(afY, bfY);             // HMMA step 1
        ldsmA(afY, bfY, sbase, 3);   // step 3 fragments
        domma(afX, bfX);             // HMMA step 2
        domma(afY, bfY);             // HMMA step 3

        if (++buf == STAGES) buf = 0;
    }

    if (EPI == 3) {
        // Complete row sums across the 4-lane k-groups (same gid), invert.
#pragma unroll
        for (int r = 0; r < 8; r++) {
            rsum[r] += __shfl_xor_sync(0xffffffffu, rsum[r], 1);
            rsum[r] += __shfl_xor_sync(0xffffffffu, rsum[r], 2);
            rsum[r] = 1.0f / rsum[r];
        }
    }

    if (EPI == 4) {
        // Transpose the CTA tile through smem, write g_vt coalesced.
        CP_WAIT_ALL();
        __syncthreads();
        __half* st = reinterpret_cast<__half*>(sm); // [n:128][m:144 halves]
#pragma unroll
        for (int i = 0; i < 4; i++) {
            const int m = wr * 64 + i * 16 + gid;
#pragma unroll
            for (int j = 0; j < 8; j++) {
                const int col = wc * 64 + j * 8 + 2 * tig;
                st[col * 144 + m]           = __float2half_rn(acc[i][j][0]);
                st[(col + 1) * 144 + m]     = __float2half_rn(acc[i][j][1]);
                st[col * 144 + m + 8]       = __float2half_rn(acc[i][j][2]);
                st[(col + 1) * 144 + m + 8] = __float2half_rn(acc[i][j][3]);
            }
        }
        __syncthreads();
        const int row = tid;        // local n (output d), one row per thread
        const int b = bm >> 11;
        const int t0 = bm & 2047;
        __half* Vt = g_vt + (size_t)b * D * T + (size_t)(bn + row) * T + t0;
#pragma unroll
        for (int c = 0; c < 16; c++) {
            const uint4 v =
                *reinterpret_cast<const uint4*>(st + row * 144 + c * 8);
            *reinterpret_cast<uint4*>(Vt + c * 8) = v;
        }
        return;
    }

    // Epilogue (EPI 1/2/3)
#pragma unroll
    for (int i = 0; i < 4; i++) {
        const int m = bm + wr * 64 + i * 16 + gid;
#pragma unroll
        for (int j = 0; j < 8; j++) {
            const int col = bn + wc * 64 + j * 8 + 2 * tig;
            if (EPI == 1) {
                __half* Ch = (__half*)Cv;
                *reinterpret_cast<__half2*>(Ch + (size_t)m * ldc + col) =
                    __floats2half2_rn(acc[i][j][0], acc[i][j][1]);
                *reinterpret_cast<__half2*>(Ch + (size_t)(m + 8) * ldc + col) =
                    __floats2half2_rn(acc[i][j][2], acc[i][j][3]);
            } else if (EPI == 2) {
                __half* Ch = (__half*)Cv;
                const float e00 = (col     <= m) ? __expf(fmaf(acc[i][j][0], SCALE, -EXPC)) : 0.0f;
                const float e01 = (col + 1 <= m) ? __expf(fmaf(acc[i][j][1], SCALE, -EXPC)) : 0.0f;
                const float e10 = (col     <= m + 8) ? __expf(fmaf(acc[i][j][2], SCALE, -EXPC)) : 0.0f;
                const float e11 = (col + 1 <= m + 8) ? __expf(fmaf(acc[i][j][3], SCALE, -EXPC)) : 0.0f;
                *reinterpret_cast<__half2*>(Ch + (size_t)m * ldc + col) =
                    __floats2half2_rn(e00, e01);
                *reinterpret_cast<__half2*>(Ch + (size_t)(m + 8) * ldc + col) =
                    __floats2half2_rn(e10, e11);
            } else {
                float* Cf = (float*)Cv;
                const float r0 = rsum[2 * i];
                const float r1 = rsum[2 * i + 1];
                *reinterpret_cast<float2*>(Cf + (size_t)m * ldc + col) =
                    make_float2(acc[i][j][0] * r0, acc[i][j][1] * r0);
                *reinterpret_cast<float2*>(Cf + (size_t)(m + 8) * ldc + col) =
                    make_float2(acc[i][j][2] * r1, acc[i][j][3] * r1);
            }
        }
    }
}

// ---------------------------------------------------------------------------
// Kernel 0a: fused fp32 -> fp16 conversions. z = 0: X, 1: Wq, 2: Wk.
// ---------------------------------------------------------------------------
__global__ __launch_bounds__(256) void cvt_kernel(const float4* __restrict__ X,
                                                  const float4* __restrict__ Wq,
                                                  const float4* __restrict__ Wk) {
    const int z = blockIdx.z;
    const float4* src = (z == 0) ? X : (z == 1) ? Wq : Wk;
    uint2* dst = reinterpret_cast<uint2*>(
        (z == 0) ? g_x : (z == 1) ? g_w16[0] : g_w16[1]);
    const int n4 = (z == 0) ? (MPROJ * D / 4) : (D * D / 4);
    const int stride = gridDim.x * blockDim.x;
    for (int i = blockIdx.x * blockDim.x + threadIdx.x; i < n4; i += stride) {
        const float4 v = src[i];
        __half2 h0 = __floats2half2_rn(v.x, v.y);
        __half2 h1 = __floats2half2_rn(v.z, v.w);
        uint2 u;
        u.x = *reinterpret_cast<uint32_t*>(&h0);
        u.y = *reinterpret_cast<uint32_t*>(&h1);
        dst[i] = u;
    }
}

// ---------------------------------------------------------------------------
// Kernel 0b: Wv fp32 [k][n] -> fp16 Wv^T [n][k], 32x32 smem tiles.
// ---------------------------------------------------------------------------
__global__ __launch_bounds__(256) void wtv_kernel(const float* __restrict__ Wv) {
    __shared__ float tile[32][33];
    const int n0 = blockIdx.x * 32, k0 = blockIdx.y * 32;
    const int c = threadIdx.x & 31, r8 = threadIdx.x >> 5;
#pragma unroll
    for (int r = r8; r < 32; r += 8)
        tile[r][c] = Wv[(size_t)(k0 + r) * D + n0 + c];
    __syncthreads();
#pragma unroll
    for (int r = r8; r < 32; r += 8)
        g_wtv[(size_t)(n0 + r) * D + k0 + c] = __float2half_rn(tile[c][r]);
}

// ---------------------------------------------------------------------------
// Kernel 1: FUSED  Mt = (Wq Wk^T)^T  (64 CTAs, scheduled first)  +
//                  V^T projection   (512 CTAs).
// grid: (8, 72). y<8 -> mt tile; y>=8 -> projv tile (EPI 4).
// ---------------------------------------------------------------------------
__global__ __launch_bounds__(NTHREADS, 2) void mtprojv_kernel() {
    if (blockIdx.y < 8) {
        // Mt[e][d] = sum_i Wk[e][i] * Wq[d][i]
        hgemm<1>(g_w16[1], g_w16[0], g_mt, D, D, D, blockIdx.y * 128,
                 blockIdx.x * 128, D / 64);
    } else {
        // V^T projection with transposed store directly into g_vt.
        hgemm<4>(g_x, g_wtv, nullptr, D, D, 0, (blockIdx.y - 8) * 128,
                 blockIdx.x * 128, D / 64);
    }
}

// ---------------------------------------------------------------------------
// Kernel 2: Y = X @ M  (NT against Mt) -> fp16. Replaces the Q projection;
// the K projection is eliminated entirely (scores = Y X^T).
// ---------------------------------------------------------------------------
__global__ __launch_bounds__(NTHREADS, 2) void projy_kernel() {
    hgemm<1>(g_x, g_mt, g_y, D, D, D, blockIdx.y * 128, blockIdx.x * 128,
             D / 64);
}

// ---------------------------------------------------------------------------
// Kernel 3: unnormalized masked probs P[b] = exp(Y X^T / 32 - 5) (causal).
// Dense triangular launch: x enumerates the 136 lower-tri (qm, kn) tiles.
// ---------------------------------------------------------------------------
__global__ __launch_bounds__(NTHREADS, 2) void scores_kernel() {
    const int l = blockIdx.x;
    int qm = (int)((sqrtf(8.0f * (float)l + 1.0f) - 1.0f) * 0.5f);
    while ((qm + 1) * (qm + 2) / 2 <= l) qm++;
    while (qm * (qm + 1) / 2 > l) qm--;
    const int kn = l - qm * (qm + 1) / 2;
    const int b = blockIdx.z;
    hgemm<2>(g_y + (size_t)b * T * D, g_x + (size_t)b * T * D,
             g_ph + (size_t)b * T * T, D, D, T, qm * 128, kn * 128, D / 64);
}

// ---------------------------------------------------------------------------
// Kernel 4: O[b] = (P[b] @ V[b]) normalized by inline row sums; k-loop
// truncated at the diagonal. Longest q-blocks launched first.
// ---------------------------------------------------------------------------
__global__ __launch_bounds__(NTHREADS, 2) void pv_kernel(float* __restrict__ O) {
    const int b = blockIdx.z;
    const int qm = (gridDim.y - 1) - blockIdx.y;
    hgemm<3>(g_ph + (size_t)b * T * T, g_vt + (size_t)b * D * T,
             O + (size_t)b * T * D, T, T, D, qm * 128, blockIdx.x * 128,
             (qm + 1) * 2);
}

// ---------------------------------------------------------------------------
extern "C" void kernel_launch(void* const* d_in, const int* in_sizes, int n_in,
                              void* d_out, int out_size) {
    (void)in_sizes; (void)n_in; (void)out_size;
    const float4* X  = (const float4*)d_in[0];
    const float4* Wq = (const float4*)d_in[1];
    const float4* Wk = (const float4*)d_in[2];
    const float*  Wv = (const float*)d_in[3];
    float* O = (float*)d_out;

    cudaFuncSetAttribute(mtprojv_kernel,
                         cudaFuncAttributeMaxDynamicSharedMemorySize,
                         SMEM_BYTES);
    cudaFuncSetAttribute(projy_kernel,
                         cudaFuncAttributeMaxDynamicSharedMemorySize,
                         SMEM_BYTES);
    cudaFuncSetAttribute(scores_kernel,
                         cudaFuncAttributeMaxDynamicSharedMemorySize,
                         SMEM_BYTES);
    cudaFuncSetAttribute(pv_kernel,
                         cudaFuncAttributeMaxDynamicSharedMemorySize,
                         SMEM_BYTES);

    cvt_kernel<<<dim3(512, 1, 3), 256>>>(X, Wq, Wk);
    wtv_kernel<<<dim3(D / 32, D / 32), 256>>>(Wv);

    mtprojv_kernel<<<dim3(8, 72), NTHREADS, SMEM_BYTES>>>();
    projy_kernel<<<dim3(D / 128, MPROJ / 128), NTHREADS, SMEM_BYTES>>>();
    scores_kernel<<<dim3(136, 1, B), NTHREADS, SMEM_BYTES>>>();
    pv_kernel<<<dim3(D / 128, T / 128, B), NTHREADS, SMEM_BYTES>>>(O);
}

// round 16
// speedup vs baseline: 1.0677x; 1.0677x over previous
#include <cuda_runtime.h>
#include <cuda_fp16.h>
#include <math.h>
#include <stdint.h>

// ---------------------------------------------------------------------------
// Problem constants
// ---------------------------------------------------------------------------
namespace {
constexpr int B = 4;
constexpr int T = 2048;
constexpr int D = 1024;      // D_IN == D_OUT
constexpr int MPROJ = B * T; // 8192

// Scratch (allocation-free: __device__ globals)
__device__ __half g_x  [(size_t)MPROJ * D];  // 16 MB  fp16 input
__device__ __half g_w16[2][(size_t)D * D];   // 4 MB   fp16 Wq, Wk (row-major)
__device__ __half g_wtv[(size_t)D * D];      // 2 MB   fp16 Wv^T (n-major)
__device__ __half g_mt [(size_t)D * D];      // 2 MB   Mt[e][d] = (Wq Wk^T)^T
__device__ __half g_y  [(size_t)B * T * D];  // 16 MB  Y = X (Wq Wk^T)
__device__ __half g_vt [(size_t)B * D * T];  // 16 MB  V^T per batch
__device__ __half g_ph [(size_t)B * T * T];  // 32 MB  unnormalized probs fp16
} // namespace

// ---------------------------------------------------------------------------
// Helpers
// ---------------------------------------------------------------------------
__device__ __forceinline__ uint32_t smem_u32(const void* p) {
    uint32_t a;
    asm("{ .reg .u64 t; cvta.to.shared.u64 t, %1; cvt.u32.u64 %0, t; }"
        : "=r"(a) : "l"(p));
    return a;
}

__device__ __forceinline__ void cp16(uint32_t dst, const void* src) {
    asm volatile("cp.async.cg.shared.global [%0], [%1], 16;"
                 :: "r"(dst), "l"(src) : "memory");
}
#define CP_COMMIT()  asm volatile("cp.async.commit_group;" ::: "memory")
#define CP_WAIT(N)   asm volatile("cp.async.wait_group %0;" :: "n"(N) : "memory")
#define CP_WAIT_ALL() asm volatile("cp.async.wait_group 0;" ::: "memory")

__device__ __forceinline__ void ldsm4(uint32_t& r0, uint32_t& r1,
                                      uint32_t& r2, uint32_t& r3,
                                      uint32_t addr) {
    asm volatile("ldmatrix.sync.aligned.m8n8.x4.shared.b16 {%0,%1,%2,%3}, [%4];"
                 : "=r"(r0), "=r"(r1), "=r"(r2), "=r"(r3) : "r"(addr));
}

__device__ __forceinline__ void mma_f16(float c[4], const uint32_t a[4],
                                        const uint32_t b[2]) {
    asm volatile(
        "mma.sync.aligned.m16n8k16.row.col.f32.f16.f16.f32 "
        "{%0,%1,%2,%3}, {%4,%5,%6,%7}, {%8,%9}, {%0,%1,%2,%3};"
        : "+f"(c[0]), "+f"(c[1]), "+f"(c[2]), "+f"(c[3])
        : "r"(a[0]), "r"(a[1]), "r"(a[2]), "r"(a[3]), "r"(b[0]), "r"(b[1]));
}

// ---------------------------------------------------------------------------
// fp16 mma.sync GEMM core ("NT": both operands K-major). R13-proven config.
//   C[m,n] += A[m,k] * Bp[n,k]
// CTA tile 128x128, BK=32 halves, 128 threads (4 warps, 2x2 grid),
// warp tile 64x64. Fragment-level software pipeline: per chunk, LDSM(step0)
// -> cp.async issue burst -> LDSM(step1) -> HMMA(step0) -> HMMA(step1).
// 5-stage cp.async pipeline; stage = 16 KB; 80 KB smem -> 2 CTAs/SM.
// EPI: 1 = plain fp16 stores
//      2 = exp(s*SCALE - EXPC) with causal mask, fp16 stores (scores)
//      3 = fp32 stores scaled by inline per-row 1/sum of A (pv)
//      4 = fp16 transposed store via smem -> g_vt (V proj)
// ---------------------------------------------------------------------------
constexpr int STAGES = 5;
constexpr int STAGE_WORDS = 4096;  // 16 KB / 4
constexpr int SMEM_BYTES = STAGES * STAGE_WORDS * 4; // 81920
constexpr int NTHREADS = 128;
constexpr float SCALE = 0.03125f;  // 1/sqrt(1024)
constexpr float EXPC = 5.0f;       // fixed exp offset (cancels in normalize)

template <int EPI>
__device__ __forceinline__ void hgemm(const __half* __restrict__ A,
                                      const __half* __restrict__ Bp,
                                      void* __restrict__ Cv,
                                      int lda, int ldb, int ldc,
                                      int bm, int bn, int nChunks) {
    extern __shared__ float sm[];
    const uint32_t smem_base = smem_u32(sm);

    const int tid = threadIdx.x;
    const int lane = tid & 31;
    const int wid = tid >> 5;
    const int wr = wid >> 1;     // 0..1  (64-row slab)
    const int wc = wid & 1;      // 0..1  (64-col slab)
    const int gid = lane >> 2;   // 0..7
    const int tig = lane & 3;    // 0..3

    // ldmatrix lane roles (mapping validated R6/R7)
    const int a_row_off = ((lane >> 3) & 1) * 8 + (lane & 7);
    const int a_kg = lane >> 4;
    const int b_row_off = (lane >> 4) * 8 + (lane & 7);
    const int b_kg = (lane >> 3) & 1;

    auto issue = [&](int chunk, int buf) {
        const int k0 = chunk * 32;
        const uint32_t sA = smem_base + (uint32_t)buf * (STAGE_WORDS * 4);
        const uint32_t sB = sA + 2048 * 4;
#pragma unroll
        for (int l = 0; l < 4; l++) {               // A: 128 rows x 32 halves
            const int idx = tid + l * NTHREADS;
            const int m = idx >> 2, c = idx & 3;
            const uint32_t sw = ((m >> 1) & 3) << 2;
            cp16(sA + (uint32_t)(m * 16 + ((4 * c) ^ sw)) * 4,
                 A + (size_t)(bm + m) * lda + k0 + 8 * c);
        }
#pragma unroll
        for (int l = 0; l < 4; l++) {               // B: 128 rows x 32 halves
            const int idx = tid + l * NTHREADS;
            const int n = idx >> 2, c = idx & 3;
            const uint32_t sw = ((n >> 1) & 3) << 2;
            cp16(sB + (uint32_t)(n * 16 + ((4 * c) ^ sw)) * 4,
                 Bp + (size_t)(bn + n) * ldb + k0 + 8 * c);
        }
    };

    float acc[4][8][4];
#pragma unroll
    for (int i = 0; i < 4; i++)
#pragma unroll
        for (int j = 0; j < 8; j++)
#pragma unroll
            for (int e = 0; e < 4; e++) acc[i][j][e] = 0.0f;

    float rsum[8]; // EPI==3: per-row A sums (rows i*16+gid, i*16+gid+8)
#pragma unroll
    for (int r = 0; r < 8; r++) rsum[r] = 0.0f;

    // Per-lane invariant fragment address pieces: low 16 = row*16, hi = swizzle
    uint32_t aw[4], bw[4];
#pragma unroll
    for (int i = 0; i < 4; i++) {
        const int row = wr * 64 + i * 16 + a_row_off;
        aw[i] = (uint32_t)(row * 16) | (((row >> 1) & 3) << 2) << 16;
    }
#pragma unroll
    for (int jp = 0; jp < 4; jp++) {
        const int row = wc * 64 + jp * 16 + b_row_off;
        bw[jp] = (uint32_t)(row * 16) | (((row >> 1) & 3) << 2) << 16;
    }

    // Prologue (nChunks >= STAGES-1 = 4 always: pv min is 4)
#pragma unroll
    for (int s = 0; s < STAGES - 1; s++) {
        issue(s, s);
        CP_COMMIT();
    }

    int buf = 0;
    for (int t = 0; t < nChunks; t++) {
        CP_WAIT(STAGES - 2);
        __syncthreads();

        const uint32_t sa = smem_base + (uint32_t)buf * (STAGE_WORDS * 4);
        const uint32_t sb = sa + 2048 * 4;

        uint32_t afA[4][4], bfA[8][2], afB[4][4], bfB[8][2];

        // ---- LDSM step 0 (w0 = 0) ----
#pragma unroll
        for (int i = 0; i < 4; i++) {
            const uint32_t g = (4 * a_kg) ^ (aw[i] >> 16);
            ldsm4(afA[i][0], afA[i][1], afA[i][2], afA[i][3],
                  sa + (((aw[i] & 0xffffu) + g) << 2));
        }
#pragma unroll
        for (int jp = 0; jp < 4; jp++) {
            const uint32_t g = (4 * b_kg) ^ (bw[jp] >> 16);
            ldsm4(bfA[2 * jp][0], bfA[2 * jp][1], bfA[2 * jp + 1][0],
                  bfA[2 * jp + 1][1], sb + (((bw[jp] & 0xffffu) + g) << 2));
        }

        // ---- independent work: prefetch chunk t+STAGES-1 (covers LDS lat) --
        if (t + STAGES - 1 < nChunks) {
            int pbuf = buf + STAGES - 1;
            if (pbuf >= STAGES) pbuf -= STAGES;
            issue(t + STAGES - 1, pbuf);
        }
        CP_COMMIT();

        // ---- LDSM step 1 (w0 = 8) ----
#pragma unroll
        for (int i = 0; i < 4; i++) {
            const uint32_t g = (8 + 4 * a_kg) ^ (aw[i] >> 16);
            ldsm4(afB[i][0], afB[i][1], afB[i][2], afB[i][3],
                  sa + (((aw[i] & 0xffffu) + g) << 2));
        }
#pragma unroll
        for (int jp = 0; jp < 4; jp++) {
            const uint32_t g = (8 + 4 * b_kg) ^ (bw[jp] >> 16);
            ldsm4(bfB[2 * jp][0], bfB[2 * jp][1], bfB[2 * jp + 1][0],
                  bfB[2 * jp + 1][1], sb + (((bw[jp] & 0xffffu) + g) << 2));
        }

        // ---- HMMA step 0 ----
        if (EPI == 3) {
#pragma unroll
            for (int i = 0; i < 4; i++) {
                const __half2 h0 = __hadd2(
                    *reinterpret_cast<__half2*>(&afA[i][0]),
                    *reinterpret_cast<__half2*>(&afA[i][2]));
                const __half2 h1 = __hadd2(
                    *reinterpret_cast<__half2*>(&afA[i][1]),
                    *reinterpret_cast<__half2*>(&afA[i][3]));
                const float2 f0 = __half22float2(h0);
                const float2 f1 = __half22float2(h1);
                rsum[2 * i]     += f0.x + f0.y;
                rsum[2 * i + 1] += f1.x + f1.y;
            }
        }
#pragma unroll
        for (int i = 0; i < 4; i++)
#pragma unroll
            for (int j = 0; j < 8; j++) mma_f16(acc[i][j], afA[i], bfA[j]);

        // ---- HMMA step 1 ----
        if (EPI == 3) {
#pragma unroll
            for (int i = 0; i < 4; i++) {
                const __half2 h0 = __hadd2(
                    *reinterpret_cast<__half2*>(&afB[i][0]),
                    *reinterpret_cast<__half2*>(&afB[i][2]));
                const __half2 h1 = __hadd2(
                    *reinterpret_cast<__half2*>(&afB[i][1]),
                    *reinterpret_cast<__half2*>(&afB[i][3]));
                const float2 f0 = __half22float2(h0);
                const float2 f1 = __half22float2(h1);
                rsum[2 * i]     += f0.x + f0.y;
                rsum[2 * i + 1] += f1.x + f1.y;
            }
        }
#pragma unroll
        for (int i = 0; i < 4; i++)
#pragma unroll
            for (int j = 0; j < 8; j++) mma_f16(acc[i][j], afB[i], bfB[j]);

        if (++buf == STAGES) buf = 0;
    }

    if (EPI == 3) {
        // Complete row sums across the 4-lane k-groups (same gid), invert.
#pragma unroll
        for (int r = 0; r < 8; r++) {
            rsum[r] += __shfl_xor_sync(0xffffffffu, rsum[r], 1);
            rsum[r] += __shfl_xor_sync(0xffffffffu, rsum[r], 2);
            rsum[r] = 1.0f / rsum[r];
        }
    }

    if (EPI == 4) {
        // Transpose the CTA tile through smem, write g_vt coalesced.
        CP_WAIT_ALL();
        __syncthreads();
        __half* st = reinterpret_cast<__half*>(sm); // [n:128][m:144 halves]
#pragma unroll
        for (int i = 0; i < 4; i++) {
            const int m = wr * 64 + i * 16 + gid;
#pragma unroll
            for (int j = 0; j < 8; j++) {
                const int col = wc * 64 + j * 8 + 2 * tig;
                st[col * 144 + m]           = __float2half_rn(acc[i][j][0]);
                st[(col + 1) * 144 + m]     = __float2half_rn(acc[i][j][1]);
                st[col * 144 + m + 8]       = __float2half_rn(acc[i][j][2]);
                st[(col + 1) * 144 + m + 8] = __float2half_rn(acc[i][j][3]);
            }
        }
        __syncthreads();
        const int row = tid;        // local n (output d), one row per thread
        const int b = bm >> 11;
        const int t0 = bm & 2047;
        __half* Vt = g_vt + (size_t)b * D * T + (size_t)(bn + row) * T + t0;
#pragma unroll
        for (int c = 0; c < 16; c++) {
            const uint4 v =
                *reinterpret_cast<const uint4*>(st + row * 144 + c * 8);
            *reinterpret_cast<uint4*>(Vt + c * 8) = v;
        }
        return;
    }

    // Epilogue (EPI 1/2/3)
#pragma unroll
    for (int i = 0; i < 4; i++) {
        const int m = bm + wr * 64 + i * 16 + gid;
#pragma unroll
        for (int j = 0; j < 8; j++) {
            const int col = bn + wc * 64 + j * 8 + 2 * tig;
            if (EPI == 1) {
                __half* Ch = (__half*)Cv;
                *reinterpret_cast<__half2*>(Ch + (size_t)m * ldc + col) =
                    __floats2half2_rn(acc[i][j][0], acc[i][j][1]);
                *reinterpret_cast<__half2*>(Ch + (size_t)(m + 8) * ldc + col) =
                    __floats2half2_rn(acc[i][j][2], acc[i][j][3]);
            } else if (EPI == 2) {
                __half* Ch = (__half*)Cv;
                const float e00 = (col     <= m) ? __expf(fmaf(acc[i][j][0], SCALE, -EXPC)) : 0.0f;
                const float e01 = (col + 1 <= m) ? __expf(fmaf(acc[i][j][1], SCALE, -EXPC)) : 0.0f;
                const float e10 = (col     <= m + 8) ? __expf(fmaf(acc[i][j][2], SCALE, -EXPC)) : 0.0f;
                const float e11 = (col + 1 <= m + 8) ? __expf(fmaf(acc[i][j][3], SCALE, -EXPC)) : 0.0f;
                *reinterpret_cast<__half2*>(Ch + (size_t)m * ldc + col) =
                    __floats2half2_rn(e00, e01);
                *reinterpret_cast<__half2*>(Ch + (size_t)(m + 8) * ldc + col) =
                    __floats2half2_rn(e10, e11);
            } else {
                float* Cf = (float*)Cv;
                const float r0 = rsum[2 * i];
                const float r1 = rsum[2 * i + 1];
                *reinterpret_cast<float2*>(Cf + (size_t)m * ldc + col) =
                    make_float2(acc[i][j][0] * r0, acc[i][j][1] * r0);
                *reinterpret_cast<float2*>(Cf + (size_t)(m + 8) * ldc + col) =
                    make_float2(acc[i][j][2] * r1, acc[i][j][3] * r1);
            }
        }
    }
}

// ---------------------------------------------------------------------------
// Kernel 0: fused prep. z = 0: X cvt, 1: Wq cvt, 2: Wk cvt, 3: Wv transpose.
// ---------------------------------------------------------------------------
__global__ __launch_bounds__(256) void prep_kernel(const float4* __restrict__ X,
                                                   const float4* __restrict__ Wq,
                                                   const float4* __restrict__ Wk,
                                                   const float* __restrict__ Wv) {
    const int z = blockIdx.z;
    if (z == 3) {
        // Wv fp32 [k][n] -> fp16 Wv^T [n][k], two 32x32 tiles per CTA.
        __shared__ float tile[32][33];
        const int c = threadIdx.x & 31, r8 = threadIdx.x >> 5;
#pragma unroll
        for (int it = 0; it < 2; it++) {
            const int tidx = blockIdx.x * 2 + it;  // 0..1023
            const int n0 = (tidx & 31) * 32, k0 = (tidx >> 5) * 32;
            __syncthreads();
#pragma unroll
            for (int r = r8; r < 32; r += 8)
                tile[r][c] = Wv[(size_t)(k0 + r) * D + n0 + c];
            __syncthreads();
#pragma unroll
            for (int r = r8; r < 32; r += 8)
                g_wtv[(size_t)(n0 + r) * D + k0 + c] =
                    __float2half_rn(tile[c][r]);
        }
        return;
    }
    const float4* src = (z == 0) ? X : (z == 1) ? Wq : Wk;
    uint2* dst = reinterpret_cast<uint2*>(
        (z == 0) ? g_x : (z == 1) ? g_w16[0] : g_w16[1]);
    const int n4 = (z == 0) ? (MPROJ * D / 4) : (D * D / 4);
    const int stride = gridDim.x * blockDim.x;
    for (int i = blockIdx.x * blockDim.x + threadIdx.x; i < n4; i += stride) {
        const float4 v = src[i];
        __half2 h0 = __floats2half2_rn(v.x, v.y);
        __half2 h1 = __floats2half2_rn(v.z, v.w);
        uint2 u;
        u.x = *reinterpret_cast<uint32_t*>(&h0);
        u.y = *reinterpret_cast<uint32_t*>(&h1);
        dst[i] = u;
    }
}

// ---------------------------------------------------------------------------
// Kernel 1: FUSED  Mt = (Wq Wk^T)^T  (64 CTAs, scheduled first)  +
//                  V^T projection   (512 CTAs).
// grid: (8, 72). y<8 -> mt tile; y>=8 -> projv tile (EPI 4).
// ---------------------------------------------------------------------------
__global__ __launch_bounds__(NTHREADS, 2) void mtprojv_kernel() {
    if (blockIdx.y < 8) {
        // Mt[e][d] = sum_i Wk[e][i] * Wq[d][i]
        hgemm<1>(g_w16[1], g_w16[0], g_mt, D, D, D, blockIdx.y * 128,
                 blockIdx.x * 128, D / 32);
    } else {
        // V^T projection with transposed store directly into g_vt.
        hgemm<4>(g_x, g_wtv, nullptr, D, D, 0, (blockIdx.y - 8) * 128,
                 blockIdx.x * 128, D / 32);
    }
}

// ---------------------------------------------------------------------------
// Kernel 2: Y = X @ M  (NT against Mt) -> fp16. Replaces the Q projection;
// the K projection is eliminated entirely (scores = Y X^T).
// ---------------------------------------------------------------------------
__global__ __launch_bounds__(NTHREADS, 2) void projy_kernel() {
    hgemm<1>(g_x, g_mt, g_y, D, D, D, blockIdx.y * 128, blockIdx.x * 128,
             D / 32);
}

// ---------------------------------------------------------------------------
// Kernel 3: unnormalized masked probs P[b] = exp(Y X^T / 32 - 5) (causal).
// Dense triangular launch: x enumerates the 136 lower-tri (qm, kn) tiles.
// ---------------------------------------------------------------------------
__global__ __launch_bounds__(NTHREADS, 2) void scores_kernel() {
    const int l = blockIdx.x;
    int qm = (int)((sqrtf(8.0f * (float)l + 1.0f) - 1.0f) * 0.5f);
    while ((qm + 1) * (qm + 2) / 2 <= l) qm++;
    while (qm * (qm + 1) / 2 > l) qm--;
    const int kn = l - qm * (qm + 1) / 2;
    const int b = blockIdx.z;
    hgemm<2>(g_y + (size_t)b * T * D, g_x + (size_t)b * T * D,
             g_ph + (size_t)b * T * T, D, D, T, qm * 128, kn * 128, D / 32);
}

// ---------------------------------------------------------------------------
// Kernel 4: O[b] = (P[b] @ V[b]) normalized by inline row sums; k-loop
// truncated at the diagonal. Longest q-blocks launched first.
// ---------------------------------------------------------------------------
__global__ __launch_bounds__(NTHREADS, 2) void pv_kernel(float* __restrict__ O) {
    const int b = blockIdx.z;
    const int qm = (gridDim.y - 1) - blockIdx.y;
    hgemm<3>(g_ph + (size_t)b * T * T, g_vt + (size_t)b * D * T,
             O + (size_t)b * T * D, T, T, D, qm * 128, blockIdx.x * 128,
             (qm + 1) * 4);
}

// ---------------------------------------------------------------------------
extern "C" void kernel_launch(void* const* d_in, const int* in_sizes, int n_in,
                              void* d_out, int out_size) {
    (void)in_sizes; (void)n_in; (void)out_size;
    const float4* X  = (const float4*)d_in[0];
    const float4* Wq = (const float4*)d_in[1];
    const float4* Wk = (const float4*)d_in[2];
    const float*  Wv = (const float*)d_in[3];
    float* O = (float*)d_out;

    cudaFuncSetAttribute(mtprojv_kernel,
                         cudaFuncAttributeMaxDynamicSharedMemorySize,
                         SMEM_BYTES);
    cudaFuncSetAttribute(projy_kernel,
                         cudaFuncAttributeMaxDynamicSharedMemorySize,
                         SMEM_BYTES);
    cudaFuncSetAttribute(scores_kernel,
                         cudaFuncAttributeMaxDynamicSharedMemorySize,
                         SMEM_BYTES);
    cudaFuncSetAttribute(pv_kernel,
                         cudaFuncAttributeMaxDynamicSharedMemorySize,
                         SMEM_BYTES);

    prep_kernel<<<dim3(512, 1, 4), 256>>>(X, Wq, Wk, Wv);

    mtprojv_kernel<<<dim3(8, 72), NTHREADS, SMEM_BYTES>>>();
    projy_kernel<<<dim3(D / 128, MPROJ / 128), NTHREADS, SMEM_BYTES>>>();
    scores_kernel<<<dim3(136, 1, B), NTHREADS, SMEM_BYTES>>>();
    pv_kernel<<<dim3(D / 128, T / 128, B), NTHREADS, SMEM_BYTES>>>(O);
}

// round 17
// speedup vs baseline: 1.0709x; 1.0030x over previous
#include <cuda_runtime.h>
#include <cuda_fp16.h>
#include <math.h>
#include <stdint.h>

// ---------------------------------------------------------------------------
// Problem constants
// ---------------------------------------------------------------------------
namespace {
constexpr int B = 4;
constexpr int T = 2048;
constexpr int D = 1024;      // D_IN == D_OUT
constexpr int MPROJ = B * T; // 8192

// Scratch (allocation-free: __device__ globals)
__device__ __half g_x  [(size_t)MPROJ * D];  // 16 MB  fp16 input
__device__ __half g_w16[2][(size_t)D * D];   // 4 MB   fp16 Wq, Wk (row-major)
__device__ __half g_wtv[(size_t)D * D];      // 2 MB   fp16 Wv^T (n-major)
__device__ __half g_mt [(size_t)D * D];      // 2 MB   Mt[e][d] = (Wq Wk^T)^T
__device__ __half g_y  [(size_t)B * T * D];  // 16 MB  Y = X (Wq Wk^T)
__device__ __half g_vt [(size_t)B * D * T];  // 16 MB  V^T per batch
__device__ __half g_ph [(size_t)B * T * T];  // 32 MB  unnormalized probs fp16
} // namespace

// ---------------------------------------------------------------------------
// Helpers
// ---------------------------------------------------------------------------
__device__ __forceinline__ uint32_t smem_u32(const void* p) {
    uint32_t a;
    asm("{ .reg .u64 t; cvta.to.shared.u64 t, %1; cvt.u32.u64 %0, t; }"
        : "=r"(a) : "l"(p));
    return a;
}

__device__ __forceinline__ void cp16(uint32_t dst, const void* src) {
    asm volatile("cp.async.cg.shared.global [%0], [%1], 16;"
                 :: "r"(dst), "l"(src) : "memory");
}
#define CP_COMMIT()  asm volatile("cp.async.commit_group;" ::: "memory")
#define CP_WAIT(N)   asm volatile("cp.async.wait_group %0;" :: "n"(N) : "memory")
#define CP_WAIT_ALL() asm volatile("cp.async.wait_group 0;" ::: "memory")

__device__ __forceinline__ void ldsm4(uint32_t& r0, uint32_t& r1,
                                      uint32_t& r2, uint32_t& r3,
                                      uint32_t addr) {
    asm volatile("ldmatrix.sync.aligned.m8n8.x4.shared.b16 {%0,%1,%2,%3}, [%4];"
                 : "=r"(r0), "=r"(r1), "=r"(r2), "=r"(r3) : "r"(addr));
}

__device__ __forceinline__ void mma_f16(float c[4], const uint32_t a[4],
                                        const uint32_t b[2]) {
    asm volatile(
        "mma.sync.aligned.m16n8k16.row.col.f32.f16.f16.f32 "
        "{%0,%1,%2,%3}, {%4,%5,%6,%7}, {%8,%9}, {%0,%1,%2,%3};"
        : "+f"(c[0]), "+f"(c[1]), "+f"(c[2]), "+f"(c[3])
        : "r"(a[0]), "r"(a[1]), "r"(a[2]), "r"(a[3]), "r"(b[0]), "r"(b[1]));
}

// ---------------------------------------------------------------------------
// fp16 mma.sync GEMM core ("NT": both operands K-major). R13-proven config.
//   C[m,n] += A[m,k] * Bp[n,k]
// CTA tile 128x128, BK=32 halves, 128 threads (4 warps, 2x2 grid),
// warp tile 64x64. Fragment-level software pipeline: per chunk, LDSM(step0)
// -> cp.async issue burst -> LDSM(step1) -> HMMA(step0) -> HMMA(step1).
// 5-stage cp.async pipeline; stage = 16 KB; 80 KB smem -> 2 CTAs/SM.
// EPI: 1 = plain fp16 stores
//      2 = exp(s*SCALE - EXPC) with causal mask, fp16 stores (scores)
//      3 = fp32 stores scaled by inline per-row 1/sum of A (pv)
//      4 = fp16 transposed store via smem -> g_vt (V proj)
// ---------------------------------------------------------------------------
constexpr int STAGES = 5;
constexpr int STAGE_WORDS = 4096;  // 16 KB / 4
constexpr int SMEM_BYTES = STAGES * STAGE_WORDS * 4; // 81920
constexpr int NTHREADS = 128;
constexpr float SCALE = 0.03125f;  // 1/sqrt(1024)
constexpr float EXPC = 5.0f;       // fixed exp offset (cancels in normalize)

template <int EPI>
__device__ __forceinline__ void hgemm(const __half* __restrict__ A,
                                      const __half* __restrict__ Bp,
                                      void* __restrict__ Cv,
                                      int lda, int ldb, int ldc,
                                      int bm, int bn, int nChunks) {
    extern __shared__ float sm[];
    const uint32_t smem_base = smem_u32(sm);

    const int tid = threadIdx.x;
    const int lane = tid & 31;
    const int wid = tid >> 5;
    const int wr = wid >> 1;     // 0..1  (64-row slab)
    const int wc = wid & 1;      // 0..1  (64-col slab)
    const int gid = lane >> 2;   // 0..7
    const int tig = lane & 3;    // 0..3

    // ldmatrix lane roles (mapping validated R6/R7)
    const int a_row_off = ((lane >> 3) & 1) * 8 + (lane & 7);
    const int a_kg = lane >> 4;
    const int b_row_off = (lane >> 4) * 8 + (lane & 7);
    const int b_kg = (lane >> 3) & 1;

    auto issue = [&](int chunk, int buf) {
        const int k0 = chunk * 32;
        const uint32_t sA = smem_base + (uint32_t)buf * (STAGE_WORDS * 4);
        const uint32_t sB = sA + 2048 * 4;
#pragma unroll
        for (int l = 0; l < 4; l++) {               // A: 128 rows x 32 halves
            const int idx = tid + l * NTHREADS;
            const int m = idx >> 2, c = idx & 3;
            const uint32_t sw = ((m >> 1) & 3) << 2;
            cp16(sA + (uint32_t)(m * 16 + ((4 * c) ^ sw)) * 4,
                 A + (size_t)(bm + m) * lda + k0 + 8 * c);
        }
#pragma unroll
        for (int l = 0; l < 4; l++) {               // B: 128 rows x 32 halves
            const int idx = tid + l * NTHREADS;
            const int n = idx >> 2, c = idx & 3;
            const uint32_t sw = ((n >> 1) & 3) << 2;
            cp16(sB + (uint32_t)(n * 16 + ((4 * c) ^ sw)) * 4,
                 Bp + (size_t)(bn + n) * ldb + k0 + 8 * c);
        }
    };

    float acc[4][8][4];
#pragma unroll
    for (int i = 0; i < 4; i++)
#pragma unroll
        for (int j = 0; j < 8; j++)
#pragma unroll
            for (int e = 0; e < 4; e++) acc[i][j][e] = 0.0f;

    float rsum[8]; // EPI==3: per-row A sums (rows i*16+gid, i*16+gid+8)
#pragma unroll
    for (int r = 0; r < 8; r++) rsum[r] = 0.0f;

    // Per-lane invariant fragment address pieces: low 16 = row*16, hi = swizzle
    uint32_t aw[4], bw[4];
#pragma unroll
    for (int i = 0; i < 4; i++) {
        const int row = wr * 64 + i * 16 + a_row_off;
        aw[i] = (uint32_t)(row * 16) | (((row >> 1) & 3) << 2) << 16;
    }
#pragma unroll
    for (int jp = 0; jp < 4; jp++) {
        const int row = wc * 64 + jp * 16 + b_row_off;
        bw[jp] = (uint32_t)(row * 16) | (((row >> 1) & 3) << 2) << 16;
    }

    // Prologue (nChunks >= STAGES-1 = 4 always: pv min is 4)
#pragma unroll
    for (int s = 0; s < STAGES - 1; s++) {
        issue(s, s);
        CP_COMMIT();
    }

    int buf = 0;
    for (int t = 0; t < nChunks; t++) {
        CP_WAIT(STAGES - 2);
        __syncthreads();

        const uint32_t sa = smem_base + (uint32_t)buf * (STAGE_WORDS * 4);
        const uint32_t sb = sa + 2048 * 4;

        uint32_t afA[4][4], bfA[8][2], afB[4][4], bfB[8][2];

        // ---- LDSM step 0 (w0 = 0) ----
#pragma unroll
        for (int i = 0; i < 4; i++) {
            const uint32_t g = (4 * a_kg) ^ (aw[i] >> 16);
            ldsm4(afA[i][0], afA[i][1], afA[i][2], afA[i][3],
                  sa + (((aw[i] & 0xffffu) + g) << 2));
        }
#pragma unroll
        for (int jp = 0; jp < 4; jp++) {
            const uint32_t g = (4 * b_kg) ^ (bw[jp] >> 16);
            ldsm4(bfA[2 * jp][0], bfA[2 * jp][1], bfA[2 * jp + 1][0],
                  bfA[2 * jp + 1][1], sb + (((bw[jp] & 0xffffu) + g) << 2));
        }

        // ---- independent work: prefetch chunk t+STAGES-1 (covers LDS lat) --
        if (t + STAGES - 1 < nChunks) {
            int pbuf = buf + STAGES - 1;
            if (pbuf >= STAGES) pbuf -= STAGES;
            issue(t + STAGES - 1, pbuf);
        }
        CP_COMMIT();

        // ---- LDSM step 1 (w0 = 8) ----
#pragma unroll
        for (int i = 0; i < 4; i++) {
            const uint32_t g = (8 + 4 * a_kg) ^ (aw[i] >> 16);
            ldsm4(afB[i][0], afB[i][1], afB[i][2], afB[i][3],
                  sa + (((aw[i] & 0xffffu) + g) << 2));
        }
#pragma unroll
        for (int jp = 0; jp < 4; jp++) {
            const uint32_t g = (8 + 4 * b_kg) ^ (bw[jp] >> 16);
            ldsm4(bfB[2 * jp][0], bfB[2 * jp][1], bfB[2 * jp + 1][0],
                  bfB[2 * jp + 1][1], sb + (((bw[jp] & 0xffffu) + g) << 2));
        }

        // ---- HMMA step 0 ----
        if (EPI == 3) {
#pragma unroll
            for (int i = 0; i < 4; i++) {
                const __half2 h0 = __hadd2(
                    *reinterpret_cast<__half2*>(&afA[i][0]),
                    *reinterpret_cast<__half2*>(&afA[i][2]));
                const __half2 h1 = __hadd2(
                    *reinterpret_cast<__half2*>(&afA[i][1]),
                    *reinterpret_cast<__half2*>(&afA[i][3]));
                const float2 f0 = __half22float2(h0);
                const float2 f1 = __half22float2(h1);
                rsum[2 * i]     += f0.x + f0.y;
                rsum[2 * i + 1] += f1.x + f1.y;
            }
        }
#pragma unroll
        for (int i = 0; i < 4; i++)
#pragma unroll
            for (int j = 0; j < 8; j++) mma_f16(acc[i][j], afA[i], bfA[j]);

        // ---- HMMA step 1 ----
        if (EPI == 3) {
#pragma unroll
            for (int i = 0; i < 4; i++) {
                const __half2 h0 = __hadd2(
                    *reinterpret_cast<__half2*>(&afB[i][0]),
                    *reinterpret_cast<__half2*>(&afB[i][2]));
                const __half2 h1 = __hadd2(
                    *reinterpret_cast<__half2*>(&afB[i][1]),
                    *reinterpret_cast<__half2*>(&afB[i][3]));
                const float2 f0 = __half22float2(h0);
                const float2 f1 = __half22float2(h1);
                rsum[2 * i]     += f0.x + f0.y;
                rsum[2 * i + 1] += f1.x + f1.y;
            }
        }
#pragma unroll
        for (int i = 0; i < 4; i++)
#pragma unroll
            for (int j = 0; j < 8; j++) mma_f16(acc[i][j], afB[i], bfB[j]);

        if (++buf == STAGES) buf = 0;
    }

    if (EPI == 3) {
        // Complete row sums across the 4-lane k-groups (same gid), invert.
#pragma unroll
        for (int r = 0; r < 8; r++) {
            rsum[r] += __shfl_xor_sync(0xffffffffu, rsum[r], 1);
            rsum[r] += __shfl_xor_sync(0xffffffffu, rsum[r], 2);
            rsum[r] = 1.0f / rsum[r];
        }
    }

    if (EPI == 4) {
        // Transpose the CTA tile through smem, write g_vt coalesced.
        CP_WAIT_ALL();
        __syncthreads();
        __half* st = reinterpret_cast<__half*>(sm); // [n:128][m:144 halves]
#pragma unroll
        for (int i = 0; i < 4; i++) {
            const int m = wr * 64 + i * 16 + gid;
#pragma unroll
            for (int j = 0; j < 8; j++) {
                const int col = wc * 64 + j * 8 + 2 * tig;
                st[col * 144 + m]           = __float2half_rn(acc[i][j][0]);
                st[(col + 1) * 144 + m]     = __float2half_rn(acc[i][j][1]);
                st[col * 144 + m + 8]       = __float2half_rn(acc[i][j][2]);
                st[(col + 1) * 144 + m + 8] = __float2half_rn(acc[i][j][3]);
            }
        }
        __syncthreads();
        const int row = tid;        // local n (output d), one row per thread
        const int b = bm >> 11;
        const int t0 = bm & 2047;
        __half* Vt = g_vt + (size_t)b * D * T + (size_t)(bn + row) * T + t0;
#pragma unroll
        for (int c = 0; c < 16; c++) {
            const uint4 v =
                *reinterpret_cast<const uint4*>(st + row * 144 + c * 8);
            *reinterpret_cast<uint4*>(Vt + c * 8) = v;
        }
        return;
    }

    // Epilogue (EPI 1/2/3)
#pragma unroll
    for (int i = 0; i < 4; i++) {
        const int m = bm + wr * 64 + i * 16 + gid;
#pragma unroll
        for (int j = 0; j < 8; j++) {
            const int col = bn + wc * 64 + j * 8 + 2 * tig;
            if (EPI == 1) {
                __half* Ch = (__half*)Cv;
                *reinterpret_cast<__half2*>(Ch + (size_t)m * ldc + col) =
                    __floats2half2_rn(acc[i][j][0], acc[i][j][1]);
                *reinterpret_cast<__half2*>(Ch + (size_t)(m + 8) * ldc + col) =
                    __floats2half2_rn(acc[i][j][2], acc[i][j][3]);
            } else if (EPI == 2) {
                __half* Ch = (__half*)Cv;
                const float e00 = (col     <= m) ? __expf(fmaf(acc[i][j][0], SCALE, -EXPC)) : 0.0f;
                const float e01 = (col + 1 <= m) ? __expf(fmaf(acc[i][j][1], SCALE, -EXPC)) : 0.0f;
                const float e10 = (col     <= m + 8) ? __expf(fmaf(acc[i][j][2], SCALE, -EXPC)) : 0.0f;
                const float e11 = (col + 1 <= m + 8) ? __expf(fmaf(acc[i][j][3], SCALE, -EXPC)) : 0.0f;
                *reinterpret_cast<__half2*>(Ch + (size_t)m * ldc + col) =
                    __floats2half2_rn(e00, e01);
                *reinterpret_cast<__half2*>(Ch + (size_t)(m + 8) * ldc + col) =
                    __floats2half2_rn(e10, e11);
            } else {
                float* Cf = (float*)Cv;
                const float r0 = rsum[2 * i];
                const float r1 = rsum[2 * i + 1];
                *reinterpret_cast<float2*>(Cf + (size_t)m * ldc + col) =
                    make_float2(acc[i][j][0] * r0, acc[i][j][1] * r0);
                *reinterpret_cast<float2*>(Cf + (size_t)(m + 8) * ldc + col) =
                    make_float2(acc[i][j][2] * r1, acc[i][j][3] * r1);
            }
        }
    }
}

// ---------------------------------------------------------------------------
// Kernel 0: fused prep. z = 0: X cvt, 1: Wq cvt, 2: Wk cvt, 3: Wv transpose.
// ---------------------------------------------------------------------------
__global__ __launch_bounds__(256) void prep_kernel(const float4* __restrict__ X,
                                                   const float4* __restrict__ Wq,
                                                   const float4* __restrict__ Wk,
                                                   const float* __restrict__ Wv) {
    const int z = blockIdx.z;
    if (z == 3) {
        // Wv fp32 [k][n] -> fp16 Wv^T [n][k], two 32x32 tiles per CTA.
        __shared__ float tile[32][33];
        const int c = threadIdx.x & 31, r8 = threadIdx.x >> 5;
#pragma unroll
        for (int it = 0; it < 2; it++) {
            const int tidx = blockIdx.x * 2 + it;  // 0..1023
            const int n0 = (tidx & 31) * 32, k0 = (tidx >> 5) * 32;
            __syncthreads();
#pragma unroll
            for (int r = r8; r < 32; r += 8)
                tile[r][c] = Wv[(size_t)(k0 + r) * D + n0 + c];
            __syncthreads();
#pragma unroll
            for (int r = r8; r < 32; r += 8)
                g_wtv[(size_t)(n0 + r) * D + k0 + c] =
                    __float2half_rn(tile[c][r]);
        }
        return;
    }
    const float4* src = (z == 0) ? X : (z == 1) ? Wq : Wk;
    uint2* dst = reinterpret_cast<uint2*>(
        (z == 0) ? g_x : (z == 1) ? g_w16[0] : g_w16[1]);
    const int n4 = (z == 0) ? (MPROJ * D / 4) : (D * D / 4);
    const int stride = gridDim.x * blockDim.x;
    for (int i = blockIdx.x * blockDim.x + threadIdx.x; i < n4; i += stride) {
        const float4 v = src[i];
        __half2 h0 = __floats2half2_rn(v.x, v.y);
        __half2 h1 = __floats2half2_rn(v.z, v.w);
        uint2 u;
        u.x = *reinterpret_cast<uint32_t*>(&h0);
        u.y = *reinterpret_cast<uint32_t*>(&h1);
        dst[i] = u;
    }
}

// ---------------------------------------------------------------------------
// Kernel 1a: Mt = (Wq Wk^T)^T.   Mt[e][d] = sum_i Wk[e][i] * Wq[d][i]
// ---------------------------------------------------------------------------
__global__ __launch_bounds__(NTHREADS, 2) void mt_kernel() {
    hgemm<1>(g_w16[1], g_w16[0], g_mt, D, D, D, blockIdx.y * 128,
             blockIdx.x * 128, D / 32);
}

// ---------------------------------------------------------------------------
// Kernel 1b (side stream): V^T projection, transposed store into g_vt.
// Runs concurrently with mt -> projy -> scores (only pv consumes g_vt).
// ---------------------------------------------------------------------------
__global__ __launch_bounds__(NTHREADS, 2) void projv_kernel() {
    hgemm<4>(g_x, g_wtv, nullptr, D, D, 0, blockIdx.y * 128,
             blockIdx.x * 128, D / 32);
}

// ---------------------------------------------------------------------------
// Kernel 2: Y = X @ M  (NT against Mt) -> fp16. Replaces the Q projection;
// the K projection is eliminated entirely (scores = Y X^T).
// ---------------------------------------------------------------------------
__global__ __launch_bounds__(NTHREADS, 2) void projy_kernel() {
    hgemm<1>(g_x, g_mt, g_y, D, D, D, blockIdx.y * 128, blockIdx.x * 128,
             D / 32);
}

// ---------------------------------------------------------------------------
// Kernel 3: unnormalized masked probs P[b] = exp(Y X^T / 32 - 5) (causal).
// Dense triangular launch: x enumerates the 136 lower-tri (qm, kn) tiles.
// ---------------------------------------------------------------------------
__global__ __launch_bounds__(NTHREADS, 2) void scores_kernel() {
    const int l = blockIdx.x;
    int qm = (int)((sqrtf(8.0f * (float)l + 1.0f) - 1.0f) * 0.5f);
    while ((qm + 1) * (qm + 2) / 2 <= l) qm++;
    while (qm * (qm + 1) / 2 > l) qm--;
    const int kn = l - qm * (qm + 1) / 2;
    const int b = blockIdx.z;
    hgemm<2>(g_y + (size_t)b * T * D, g_x + (size_t)b * T * D,
             g_ph + (size_t)b * T * T, D, D, T, qm * 128, kn * 128, D / 32);
}

// ---------------------------------------------------------------------------
// Kernel 4: O[b] = (P[b] @ V[b]) normalized by inline row sums; k-loop
// truncated at the diagonal. Longest q-blocks launched first.
// ---------------------------------------------------------------------------
__global__ __launch_bounds__(NTHREADS, 2) void pv_kernel(float* __restrict__ O) {
    const int b = blockIdx.z;
    const int qm = (gridDim.y - 1) - blockIdx.y;
    hgemm<3>(g_ph + (size_t)b * T * T, g_vt + (size_t)b * D * T,
             O + (size_t)b * T * D, T, T, D, qm * 128, blockIdx.x * 128,
             (qm + 1) * 4);
}

// ---------------------------------------------------------------------------
extern "C" void kernel_launch(void* const* d_in, const int* in_sizes, int n_in,
                              void* d_out, int out_size) {
    (void)in_sizes; (void)n_in; (void)out_size;
    const float4* X  = (const float4*)d_in[0];
    const float4* Wq = (const float4*)d_in[1];
    const float4* Wk = (const float4*)d_in[2];
    const float*  Wv = (const float*)d_in[3];
    float* O = (float*)d_out;

    cudaFuncSetAttribute(mt_kernel,
                         cudaFuncAttributeMaxDynamicSharedMemorySize,
                         SMEM_BYTES);
    cudaFuncSetAttribute(projv_kernel,
                         cudaFuncAttributeMaxDynamicSharedMemorySize,
                         SMEM_BYTES);
    cudaFuncSetAttribute(projy_kernel,
                         cudaFuncAttributeMaxDynamicSharedMemorySize,
                         SMEM_BYTES);
    cudaFuncSetAttribute(scores_kernel,
                         cudaFuncAttributeMaxDynamicSharedMemorySize,
                         SMEM_BYTES);
    cudaFuncSetAttribute(pv_kernel,
                         cudaFuncAttributeMaxDynamicSharedMemorySize,
                         SMEM_BYTES);

    // Fork/join stream pattern (capture-safe; streams/events created per call
    // and intentionally not destroyed — host-side only, a handful of calls).
    cudaStream_t s1;
    cudaEvent_t evPrep, evVt;
    cudaStreamCreateWithFlags(&s1, cudaStreamNonBlocking);
    cudaEventCreateWithFlags(&evPrep, cudaEventDisableTiming);
    cudaEventCreateWithFlags(&evVt, cudaEventDisableTiming);

    prep_kernel<<<dim3(512, 1, 4), 256>>>(X, Wq, Wk, Wv);
    cudaEventRecord(evPrep, 0);

    // Side branch: V^T projection (consumed only by pv).
    cudaStreamWaitEvent(s1, evPrep, 0);
    projv_kernel<<<dim3(8, 64), NTHREADS, SMEM_BYTES, s1>>>();
    cudaEventRecord(evVt, s1);

    // Main branch: mt -> projy -> scores.
    mt_kernel<<<dim3(8, 8), NTHREADS, SMEM_BYTES>>>();
    projy_kernel<<<dim3(D / 128, MPROJ / 128), NTHREADS, SMEM_BYTES>>>();
    scores_kernel<<<dim3(136, 1, B), NTHREADS, SMEM_BYTES>>>();

    // Join: pv needs both scores (main) and g_vt (side).
    cudaStreamWaitEvent(0, evVt, 0);
    pv_kernel<<<dim3(D / 128, T / 128, B), NTHREADS, SMEM_BYTES>>>(O);
}